// round 16
// baseline (speedup 1.0000x reference)
#include <cuda_runtime.h>
#include <cuda_bf16.h>
#include <cstdint>
#include <cstddef>

// TMPNN: 7 steps of x += poly(x) @ W, M=131072, N=32, symmetric-folded basis.
// R16 (= R15 design, template rewrite after macro compile failure):
//  - M=32 rows/warp B-fragment reuse at 24 warps/SM via n-pass splitting:
//    each step = pass A (n 0..15, BfL) + pass B (n 16..31, BfH); per-pass res
//    is 16 regs; fp32 residual state in SMEM xs (epilogues: xs += res).
//  - Cyclic 4-slot window, one scalar LDS per d-group; all window indices are
//    template-constexpr (no dynamic register-array indexing).
//  - B table byte-identical to R11/R13 (shift-orbit covering, K=624, dups W=0).
//  - Last step: pass A only, nt0 only, uint2 B loads, direct out write.

namespace {

constexpr int NKT   = 39;            // k-tiles of 16 (K_mma = 624)
constexpr int XBSTR = 21;            // xsb row stride (u32)
constexpr int XSSTR = 34;            // xs row stride (fp32)
constexpr int ROWS  = 256;           // rows per CTA (8 warps x 32 rows)

constexpr int OFF_XS = 0;                               // float xs[256][34]
constexpr int OFF_XB = ROWS * XSSTR * 4;                // u32 xsb[256][21]
constexpr int SMEM_BYTES = OFF_XB + ROWS * XBSTR * 4;   // 56320 -> 3 CTAs/SM

__device__ __forceinline__ uint32_t pack2(float lo, float hi) {
    uint32_t r;
    asm("cvt.rn.bf16x2.f32 %0, %1, %2;" : "=r"(r) : "f"(hi), "f"(lo));
    return r;
}

__device__ __forceinline__ void mma16816(float* c, uint32_t a0, uint32_t a1,
                                         uint32_t a2, uint32_t a3,
                                         uint32_t b0, uint32_t b1) {
    asm volatile("mma.sync.aligned.m16n8k16.row.col.f32.bf16.bf16.f32 "
                 "{%0,%1,%2,%3}, {%4,%5,%6,%7}, {%8,%9}, {%0,%1,%2,%3};"
                 : "+f"(c[0]), "+f"(c[1]), "+f"(c[2]), "+f"(c[3])
                 : "r"(a0), "r"(a1), "r"(a2), "r"(a3), "r"(b0), "r"(b1));
}

// quad A-frag: u = broadcast half (hi? upper : lower) of b; v = w. One HMUL2.
__device__ __forceinline__ uint32_t qfrag(uint32_t b, uint32_t v, int hi) {
    const uint32_t u = __byte_perm(b, b, hi ? 0x3232 : 0x1010);
    uint32_t r;
    asm("mul.rn.bf16x2 %0, %1, %2;" : "=r"(r) : "r"(u), "r"(v));
    return r;
}

// quad tile T: G=T>>2 (d-group), a=T&3. u from base[s][a] (halves 0 and 1),
// v = y[a+G] = base[s][a] (G==0) or window slot (G+a)&3. Both n-tiles of pass.
template <int T>
__device__ __forceinline__ void qt(const uint32_t (&base)[4][4],
                                   const uint32_t (&win)[4][4],
                                   float (&res)[2][2][4], const uint4* BT) {
    constexpr int G = T >> 2, a = T & 3, wi = (G + a) & 3;
    const uint4 qv = __ldg(BT + T * 32);
    uint32_t v0 = (G == 0) ? base[0][a] : win[0][wi];
    uint32_t v1 = (G == 0) ? base[1][a] : win[1][wi];
    uint32_t f0 = qfrag(base[0][a], v0, 0);
    uint32_t f1 = qfrag(base[1][a], v1, 0);
    uint32_t f2 = qfrag(base[0][a], v0, 1);
    uint32_t f3 = qfrag(base[1][a], v1, 1);
    mma16816(res[0][0], f0, f1, f2, f3, qv.x, qv.y);
    mma16816(res[0][1], f0, f1, f2, f3, qv.z, qv.w);
    v0 = (G == 0) ? base[2][a] : win[2][wi];
    v1 = (G == 0) ? base[3][a] : win[3][wi];
    f0 = qfrag(base[2][a], v0, 0);
    f1 = qfrag(base[3][a], v1, 0);
    f2 = qfrag(base[2][a], v0, 1);
    f3 = qfrag(base[3][a], v1, 1);
    mma16816(res[1][0], f0, f1, f2, f3, qv.x, qv.y);
    mma16816(res[1][1], f0, f1, f2, f3, qv.z, qv.w);
}

template <int T0>
__device__ __forceinline__ void qt4(const uint32_t (&base)[4][4],
                                    const uint32_t (&win)[4][4],
                                    float (&res)[2][2][4], const uint4* BT) {
    qt<T0>(base, win, res, BT);
    qt<T0 + 1>(base, win, res, BT);
    qt<T0 + 2>(base, win, res, BT);
    qt<T0 + 3>(base, win, res, BT);
}

// advance window for group G: dead slot (G+3)&3 <- y[G+3] (one LDS per slice)
template <int G>
__device__ __forceinline__ void wload(uint32_t (&win)[4][4],
                                      const uint32_t* xsb, int r0, int c) {
    constexpr int slot = (G + 3) & 3;
    #pragma unroll
    for (int s = 0; s < 4; ++s)
        win[s][slot] = xsb[(r0 + 8 * s) * XBSTR + ((G + 3 + 4 * c) & 15)];
}

// linear tile: frags are natural pairs base[s][I0], base[s][I1]
template <int T, int I0, int I1>
__device__ __forceinline__ void lt(const uint32_t (&base)[4][4],
                                   float (&res)[2][2][4], const uint4* BT) {
    const uint4 qv = __ldg(BT + T * 32);
    mma16816(res[0][0], base[0][I0], base[1][I0], base[0][I1], base[1][I1], qv.x, qv.y);
    mma16816(res[0][1], base[0][I0], base[1][I0], base[0][I1], base[1][I1], qv.z, qv.w);
    mma16816(res[1][0], base[2][I0], base[3][I0], base[2][I1], base[3][I1], qv.x, qv.y);
    mma16816(res[1][1], base[2][I0], base[3][I0], base[2][I1], base[3][I1], qv.z, qv.w);
}

__device__ __forceinline__ void run_pass(const uint4* BT,
                                         const uint32_t (&base)[4][4],
                                         float (&res)[2][2][4],
                                         const uint32_t* xsb, int r0, int c) {
    uint32_t win[4][4];
    #pragma unroll
    for (int s = 0; s < 4; ++s) {
        win[s][0] = base[s][0]; win[s][1] = base[s][1];
        win[s][2] = base[s][2]; win[s][3] = base[s][3];
    }
    qt4<0>(base, win, res, BT);   wload<1>(win, xsb, r0, c);
    qt4<4>(base, win, res, BT);   wload<2>(win, xsb, r0, c);
    qt4<8>(base, win, res, BT);   wload<3>(win, xsb, r0, c);
    qt4<12>(base, win, res, BT);  wload<4>(win, xsb, r0, c);
    qt4<16>(base, win, res, BT);  wload<5>(win, xsb, r0, c);
    qt4<20>(base, win, res, BT);  wload<6>(win, xsb, r0, c);
    qt4<24>(base, win, res, BT);  wload<7>(win, xsb, r0, c);
    qt4<28>(base, win, res, BT);  wload<8>(win, xsb, r0, c);
    qt4<32>(base, win, res, BT);
    lt<36, 0, 1>(base, res, BT);
    lt<37, 2, 3>(base, res, BT);
    {   // tile 38: slot 76 = {bias=1, 0}; slot 77 = zero pad
        const uint4 qv = __ldg(BT + 38 * 32);
        const uint32_t ab = 0x00003F80u, az = 0u;
        mma16816(res[0][0], ab, ab, az, az, qv.x, qv.y);
        mma16816(res[0][1], ab, ab, az, az, qv.z, qv.w);
        mma16816(res[1][0], ab, ab, az, az, qv.x, qv.y);
        mma16816(res[1][1], ab, ab, az, az, qv.z, qv.w);
    }
}

// ---- final-step variants: nt0 only, uint2 B loads (BT2 = uint2 view) ----
template <int T>
__device__ __forceinline__ void qtf(const uint32_t (&base)[4][4],
                                    const uint32_t (&win)[4][4],
                                    float (&res)[2][4], const uint2* BT2) {
    constexpr int G = T >> 2, a = T & 3, wi = (G + a) & 3;
    const uint2 qv = __ldg(BT2 + T * 64);
    uint32_t v0 = (G == 0) ? base[0][a] : win[0][wi];
    uint32_t v1 = (G == 0) ? base[1][a] : win[1][wi];
    mma16816(res[0], qfrag(base[0][a], v0, 0), qfrag(base[1][a], v1, 0),
             qfrag(base[0][a], v0, 1), qfrag(base[1][a], v1, 1), qv.x, qv.y);
    v0 = (G == 0) ? base[2][a] : win[2][wi];
    v1 = (G == 0) ? base[3][a] : win[3][wi];
    mma16816(res[1], qfrag(base[2][a], v0, 0), qfrag(base[3][a], v1, 0),
             qfrag(base[2][a], v0, 1), qfrag(base[3][a], v1, 1), qv.x, qv.y);
}

template <int T0>
__device__ __forceinline__ void qtf4(const uint32_t (&base)[4][4],
                                     const uint32_t (&win)[4][4],
                                     float (&res)[2][4], const uint2* BT2) {
    qtf<T0>(base, win, res, BT2);
    qtf<T0 + 1>(base, win, res, BT2);
    qtf<T0 + 2>(base, win, res, BT2);
    qtf<T0 + 3>(base, win, res, BT2);
}

// ---- runtime W for B-table init (identical to R11/R13; dups get 0) ----
__device__ float wsym(const float* __restrict__ W, int i, int m, int n) {
    if (i == m) return __ldg(&W[(33 + i * 32 + i) * 32 + n]);
    return __ldg(&W[(33 + i * 32 + m) * 32 + n]) + __ldg(&W[(33 + m * 32 + i) * 32 + n]);
}

__device__ float wcell(const float* __restrict__ W, int S, int c, int j, int n) {
    if (S >= 77) return 0.0f;
    if (S == 76) return (j == 0 && c == 0) ? __ldg(&W[n]) : 0.0f;
    if (S >= 72) {
        const int pv = ((S - 72) + 4 * c) & 15;
        return __ldg(&W[(1 + 2 * pv + j) * 32 + n]);
    }
    const int d = S >> 3, a = (S >> 1) & 3, h = S & 1;
    const int A = (a + 4 * c) & 15;
    if (d == 0) {
        if (h == 1 && j == 0) return 0.0f;           // dup {2A+1, 2A}
        return wsym(W, 2 * A + h, 2 * A + j, n);
    }
    if (d == 8 && A >= 8) return 0.0f;               // reversed copy of {A-8, A}
    const int B = (A + d) & 15;
    return wsym(W, 2 * A + h, 2 * B + j, n);
}

} // namespace

// B-fragment tables: [0, NKT*32) = Lo (n 0..15), [NKT*32, 2*NKT*32) = Hi.
__device__ uint4 g_Bf[2 * NKT * 32];

__global__ void bf_init_kernel(const float* __restrict__ W) {
    const int idx = blockIdx.x * blockDim.x + threadIdx.x;
    if (idx >= 2 * NKT * 32) return;
    const int t   = idx / (NKT * 32);
    const int rem = idx - t * (NKT * 32);
    const int kt  = rem >> 5;
    const int l   = rem & 31;
    const int c   = l & 3;
    const int n0  = (l >> 2) + t * 16;
    uint4 q;
    q.x = pack2(wcell(W, 2 * kt,     c, 0, n0),     wcell(W, 2 * kt,     c, 1, n0));
    q.y = pack2(wcell(W, 2 * kt + 1, c, 0, n0),     wcell(W, 2 * kt + 1, c, 1, n0));
    q.z = pack2(wcell(W, 2 * kt,     c, 0, n0 + 8), wcell(W, 2 * kt,     c, 1, n0 + 8));
    q.w = pack2(wcell(W, 2 * kt + 1, c, 0, n0 + 8), wcell(W, 2 * kt + 1, c, 1, n0 + 8));
    g_Bf[idx] = q;
}

__global__ void __launch_bounds__(256, 3)
tmpnn_kernel(const float* __restrict__ X, float* __restrict__ out)
{
    extern __shared__ char smem[];
    float*    xs  = reinterpret_cast<float*>(smem + OFF_XS);    // fp32 state
    uint32_t* xsb = reinterpret_cast<uint32_t*>(smem + OFF_XB); // bf16x2 copy

    const int tid  = threadIdx.x;
    const int lane = tid & 31;
    const int w    = tid >> 5;
    const int c    = lane & 3;               // fragment column group / rotation
    const int r0   = w * 32 + (lane >> 2);   // rows r0, +8, +16, +24
    const int cb   = c * 2;                  // accumulator col base

    // ---- stage fp32 state + bf16x2 copy ----
    const float* Xb = X + (size_t)blockIdx.x * (ROWS * 32);
    for (int i = tid; i < ROWS * 32; i += 256)
        xs[(i >> 5) * XSSTR + (i & 31)] = Xb[i];
    for (int i = tid; i < ROWS * 16; i += 256) {
        const int rr = i >> 4, j = i & 15;
        const float2 v = __ldg(reinterpret_cast<const float2*>(Xb + rr * 32 + 2 * j));
        xsb[rr * XBSTR + j] = pack2(v.x, v.y);
    }
    __syncthreads();   // only CTA-wide barrier

    const uint4* BfL = g_Bf + lane;
    const uint4* BfH = g_Bf + (NKT * 32) + lane;

    for (int step = 0; step < 6; ++step) {
        // base = y[0..3] for the 4 row slices
        uint32_t base[4][4];
        #pragma unroll
        for (int s = 0; s < 4; ++s) {
            const int rr = r0 + 8 * s;
            #pragma unroll
            for (int i2 = 0; i2 < 4; ++i2)
                base[s][i2] = xsb[rr * XBSTR + ((i2 + 4 * c) & 15)];
        }

        // ---- pass A: n 0..15 ----
        float resA[2][2][4];
        #pragma unroll
        for (int g = 0; g < 2; ++g)
            #pragma unroll
            for (int nt = 0; nt < 2; ++nt)
                #pragma unroll
                for (int q = 0; q < 4; ++q) resA[g][nt][q] = 0.0f;
        run_pass(BfL, base, resA, xsb, r0, c);

        // epilogue A: xs += resA; hold packed bf16x2 until pass-B reads done
        uint32_t pk[8];
        #pragma unroll
        for (int g = 0; g < 2; ++g)
            #pragma unroll
            for (int nt = 0; nt < 2; ++nt) {
                const int cc = nt * 8 + cb, rg = r0 + 16 * g;
                float2* p0 = reinterpret_cast<float2*>(&xs[rg * XSSTR + cc]);
                float2* p1 = reinterpret_cast<float2*>(&xs[(rg + 8) * XSSTR + cc]);
                float2 v0 = *p0, v1 = *p1;
                v0.x += resA[g][nt][0]; v0.y += resA[g][nt][1];
                v1.x += resA[g][nt][2]; v1.y += resA[g][nt][3];
                *p0 = v0; *p1 = v1;
                pk[(g * 2 + nt) * 2 + 0] = pack2(v0.x, v0.y);
                pk[(g * 2 + nt) * 2 + 1] = pack2(v1.x, v1.y);
            }

        // ---- pass B: n 16..31 ----
        float resB[2][2][4];
        #pragma unroll
        for (int g = 0; g < 2; ++g)
            #pragma unroll
            for (int nt = 0; nt < 2; ++nt)
                #pragma unroll
                for (int q = 0; q < 4; ++q) resB[g][nt][q] = 0.0f;
        run_pass(BfH, base, resB, xsb, r0, c);

        __syncwarp();   // all pass-B xsb reads done before overwrite
        #pragma unroll
        for (int g = 0; g < 2; ++g)
            #pragma unroll
            for (int nt = 0; nt < 2; ++nt) {
                const int cc = 16 + nt * 8 + cb, rg = r0 + 16 * g;
                float2* p0 = reinterpret_cast<float2*>(&xs[rg * XSSTR + cc]);
                float2* p1 = reinterpret_cast<float2*>(&xs[(rg + 8) * XSSTR + cc]);
                float2 v0 = *p0, v1 = *p1;
                v0.x += resB[g][nt][0]; v0.y += resB[g][nt][1];
                v1.x += resB[g][nt][2]; v1.y += resB[g][nt][3];
                *p0 = v0; *p1 = v1;
                xsb[rg * XBSTR + (8 + nt * 4 + c)]       = pack2(v0.x, v0.y);
                xsb[(rg + 8) * XBSTR + (8 + nt * 4 + c)] = pack2(v1.x, v1.y);
                xsb[rg * XBSTR + (nt * 4 + c)]       = pk[(g * 2 + nt) * 2 + 0];
                xsb[(rg + 8) * XBSTR + (nt * 4 + c)] = pk[(g * 2 + nt) * 2 + 1];
            }
        __syncwarp();   // visible to next step's loads
    }

    // ---- final step: pass A only, nt0 only (output col 0) ----
    {
        uint32_t base[4][4];
        #pragma unroll
        for (int s = 0; s < 4; ++s) {
            const int rr = r0 + 8 * s;
            #pragma unroll
            for (int i2 = 0; i2 < 4; ++i2)
                base[s][i2] = xsb[rr * XBSTR + ((i2 + 4 * c) & 15)];
        }
        float resF[2][4];
        #pragma unroll
        for (int g = 0; g < 2; ++g)
            #pragma unroll
            for (int q = 0; q < 4; ++q) resF[g][q] = 0.0f;

        const uint2* BT2 = reinterpret_cast<const uint2*>(g_Bf) + lane * 2;
        uint32_t win[4][4];
        #pragma unroll
        for (int s = 0; s < 4; ++s) {
            win[s][0] = base[s][0]; win[s][1] = base[s][1];
            win[s][2] = base[s][2]; win[s][3] = base[s][3];
        }
        qtf4<0>(base, win, resF, BT2);   wload<1>(win, xsb, r0, c);
        qtf4<4>(base, win, resF, BT2);   wload<2>(win, xsb, r0, c);
        qtf4<8>(base, win, resF, BT2);   wload<3>(win, xsb, r0, c);
        qtf4<12>(base, win, resF, BT2);  wload<4>(win, xsb, r0, c);
        qtf4<16>(base, win, resF, BT2);  wload<5>(win, xsb, r0, c);
        qtf4<20>(base, win, resF, BT2);  wload<6>(win, xsb, r0, c);
        qtf4<24>(base, win, resF, BT2);  wload<7>(win, xsb, r0, c);
        qtf4<28>(base, win, resF, BT2);  wload<8>(win, xsb, r0, c);
        qtf4<32>(base, win, resF, BT2);
        {   // linear tiles 36, 37 + bias 38 (nt0 only)
            const uint2 q36 = __ldg(BT2 + 36 * 64);
            mma16816(resF[0], base[0][0], base[1][0], base[0][1], base[1][1], q36.x, q36.y);
            mma16816(resF[1], base[2][0], base[3][0], base[2][1], base[3][1], q36.x, q36.y);
            const uint2 q37 = __ldg(BT2 + 37 * 64);
            mma16816(resF[0], base[0][2], base[1][2], base[0][3], base[1][3], q37.x, q37.y);
            mma16816(resF[1], base[2][2], base[3][2], base[2][3], base[3][3], q37.x, q37.y);
            const uint2 q38 = __ldg(BT2 + 38 * 64);
            const uint32_t ab = 0x00003F80u, az = 0u;
            mma16816(resF[0], ab, ab, az, az, q38.x, q38.y);
            mma16816(resF[1], ab, ab, az, az, q38.x, q38.y);
        }

        if (c == 0) {
            const size_t ob = (size_t)blockIdx.x * ROWS;
            #pragma unroll
            for (int g = 0; g < 2; ++g) {
                const int rg = r0 + 16 * g;
                out[ob + rg]     = xs[rg * XSSTR] + resF[g][0];
                out[ob + rg + 8] = xs[(rg + 8) * XSSTR] + resF[g][2];
            }
        }
    }
}

extern "C" void kernel_launch(void* const* d_in, const int* in_sizes, int n_in,
                              void* d_out, int out_size) {
    const float* X = (const float*)d_in[0];
    const float* W = (const float*)d_in[1];
    float* out = (float*)d_out;
    const int rows = in_sizes[0] / 32;
    const int blocks = rows / ROWS;
    bf_init_kernel<<<(2 * NKT * 32 + 255) / 256, 256>>>(W);
    cudaFuncSetAttribute(tmpnn_kernel, cudaFuncAttributeMaxDynamicSharedMemorySize,
                         SMEM_BYTES);
    tmpnn_kernel<<<blocks, 256, SMEM_BYTES>>>(X, out);
}

// round 17
// speedup vs baseline: 2.7787x; 2.7787x over previous
#include <cuda_runtime.h>
#include <cuda_bf16.h>
#include <cstdint>
#include <cstddef>

// TMPNN: 7 steps of x += poly(x) @ W, M=131072, N=32, symmetric-folded basis.
// R17: warp-PAIR n-split. Even warp of each pair computes n 0..15 (BfL only),
// odd warp n 16..31 (BfH only), over the same 32 rows -> per-warp B traffic
// halves vs R11 with NO extra accumulators (16-reg state per warp, carried in
// MMA accumulators). A-frag HMUL2 work duplicated across the pair (fma has
// headroom). x exchanged via double-buffered bf16x2 xsb + one named barrier
// per step. B table byte-identical to R11/R13/R16 (shift-orbit covering,
// K=624, dups W=0). Last step: even warps only, nt0, uint2 B loads.

namespace {

constexpr int NKT   = 39;            // k-tiles of 16 (K_mma = 624)
constexpr int XBSTR = 20;            // xsb row stride (u32) -> uint4-aligned rows
constexpr int ROWS  = 128;           // rows per CTA (4 pairs x 32 rows)
constexpr int XB_BUF = ROWS * XBSTR;             // u32 per buffer
constexpr int SMEM_BYTES = 2 * XB_BUF * 4;       // 20480 -> 3 CTAs/SM

__device__ __forceinline__ uint32_t pack2(float lo, float hi) {
    uint32_t r;
    asm("cvt.rn.bf16x2.f32 %0, %1, %2;" : "=r"(r) : "f"(hi), "f"(lo));
    return r;
}

__device__ __forceinline__ void mma16816(float* c, uint32_t a0, uint32_t a1,
                                         uint32_t a2, uint32_t a3,
                                         uint32_t b0, uint32_t b1) {
    asm volatile("mma.sync.aligned.m16n8k16.row.col.f32.bf16.bf16.f32 "
                 "{%0,%1,%2,%3}, {%4,%5,%6,%7}, {%8,%9}, {%0,%1,%2,%3};"
                 : "+f"(c[0]), "+f"(c[1]), "+f"(c[2]), "+f"(c[3])
                 : "r"(a0), "r"(a1), "r"(a2), "r"(a3), "r"(b0), "r"(b1));
}

// quad A-frag: u = broadcast half (hi? upper : lower) of b; v = w. One HMUL2.
__device__ __forceinline__ uint32_t qfrag(uint32_t b, uint32_t v, int hi) {
    const uint32_t u = __byte_perm(b, b, hi ? 0x3232 : 0x1010);
    uint32_t r;
    asm("mul.rn.bf16x2 %0, %1, %2;" : "=r"(r) : "r"(u), "r"(v));
    return r;
}

// quad tile T: G=T>>2 (d-group), a=T&3. u from base[s][a] (halves 0/1),
// v = y[a+G] = base[s][a] (G==0) or window slot (G+a)&3. Both n-tiles.
template <int T>
__device__ __forceinline__ void qt(const uint32_t (&base)[4][4],
                                   const uint32_t (&win)[4][4],
                                   float (&res)[2][2][4], const uint4* BT) {
    constexpr int G = T >> 2, a = T & 3, wi = (G + a) & 3;
    const uint4 qv = __ldg(BT + T * 32);
    uint32_t v0 = (G == 0) ? base[0][a] : win[0][wi];
    uint32_t v1 = (G == 0) ? base[1][a] : win[1][wi];
    uint32_t f0 = qfrag(base[0][a], v0, 0);
    uint32_t f1 = qfrag(base[1][a], v1, 0);
    uint32_t f2 = qfrag(base[0][a], v0, 1);
    uint32_t f3 = qfrag(base[1][a], v1, 1);
    mma16816(res[0][0], f0, f1, f2, f3, qv.x, qv.y);
    mma16816(res[0][1], f0, f1, f2, f3, qv.z, qv.w);
    v0 = (G == 0) ? base[2][a] : win[2][wi];
    v1 = (G == 0) ? base[3][a] : win[3][wi];
    f0 = qfrag(base[2][a], v0, 0);
    f1 = qfrag(base[3][a], v1, 0);
    f2 = qfrag(base[2][a], v0, 1);
    f3 = qfrag(base[3][a], v1, 1);
    mma16816(res[1][0], f0, f1, f2, f3, qv.x, qv.y);
    mma16816(res[1][1], f0, f1, f2, f3, qv.z, qv.w);
}

template <int T0>
__device__ __forceinline__ void qt4(const uint32_t (&base)[4][4],
                                    const uint32_t (&win)[4][4],
                                    float (&res)[2][2][4], const uint4* BT) {
    qt<T0>(base, win, res, BT);
    qt<T0 + 1>(base, win, res, BT);
    qt<T0 + 2>(base, win, res, BT);
    qt<T0 + 3>(base, win, res, BT);
}

// advance window for group G: dead slot (G+3)&3 <- y[G+3] (one LDS per slice)
template <int G>
__device__ __forceinline__ void wload(uint32_t (&win)[4][4],
                                      const uint32_t* xb, int r0, int c) {
    constexpr int slot = (G + 3) & 3;
    #pragma unroll
    for (int s = 0; s < 4; ++s)
        win[s][slot] = xb[(r0 + 8 * s) * XBSTR + ((G + 3 + 4 * c) & 15)];
}

// linear tile: frags are natural pairs base[s][I0], base[s][I1]
template <int T, int I0, int I1>
__device__ __forceinline__ void lt(const uint32_t (&base)[4][4],
                                   float (&res)[2][2][4], const uint4* BT) {
    const uint4 qv = __ldg(BT + T * 32);
    mma16816(res[0][0], base[0][I0], base[1][I0], base[0][I1], base[1][I1], qv.x, qv.y);
    mma16816(res[0][1], base[0][I0], base[1][I0], base[0][I1], base[1][I1], qv.z, qv.w);
    mma16816(res[1][0], base[2][I0], base[3][I0], base[2][I1], base[3][I1], qv.x, qv.y);
    mma16816(res[1][1], base[2][I0], base[3][I0], base[2][I1], base[3][I1], qv.z, qv.w);
}

// full pass: accumulate this warp's n-half over all 39 k-tiles into res
__device__ __forceinline__ void run_pass(const uint4* BT,
                                         const uint32_t (&base)[4][4],
                                         float (&res)[2][2][4],
                                         const uint32_t* xb, int r0, int c) {
    uint32_t win[4][4];
    #pragma unroll
    for (int s = 0; s < 4; ++s) {
        win[s][0] = base[s][0]; win[s][1] = base[s][1];
        win[s][2] = base[s][2]; win[s][3] = base[s][3];
    }
    qt4<0>(base, win, res, BT);   wload<1>(win, xb, r0, c);
    qt4<4>(base, win, res, BT);   wload<2>(win, xb, r0, c);
    qt4<8>(base, win, res, BT);   wload<3>(win, xb, r0, c);
    qt4<12>(base, win, res, BT);  wload<4>(win, xb, r0, c);
    qt4<16>(base, win, res, BT);  wload<5>(win, xb, r0, c);
    qt4<20>(base, win, res, BT);  wload<6>(win, xb, r0, c);
    qt4<24>(base, win, res, BT);  wload<7>(win, xb, r0, c);
    qt4<28>(base, win, res, BT);  wload<8>(win, xb, r0, c);
    qt4<32>(base, win, res, BT);
    lt<36, 0, 1>(base, res, BT);
    lt<37, 2, 3>(base, res, BT);
    {   // tile 38: slot 76 = {bias=1, 0}; slot 77 = zero pad
        const uint4 qv = __ldg(BT + 38 * 32);
        const uint32_t ab = 0x00003F80u, az = 0u;
        mma16816(res[0][0], ab, ab, az, az, qv.x, qv.y);
        mma16816(res[0][1], ab, ab, az, az, qv.z, qv.w);
        mma16816(res[1][0], ab, ab, az, az, qv.x, qv.y);
        mma16816(res[1][1], ab, ab, az, az, qv.z, qv.w);
    }
}

// ---- final-step quad tile: nt0 only (cols 0..7), uint2 B loads ----
template <int T>
__device__ __forceinline__ void qtf(const uint32_t (&base)[4][4],
                                    const uint32_t (&win)[4][4],
                                    float (&res)[2][2][4], const uint2* BT2) {
    constexpr int G = T >> 2, a = T & 3, wi = (G + a) & 3;
    const uint2 qv = __ldg(BT2 + T * 64);
    uint32_t v0 = (G == 0) ? base[0][a] : win[0][wi];
    uint32_t v1 = (G == 0) ? base[1][a] : win[1][wi];
    mma16816(res[0][0], qfrag(base[0][a], v0, 0), qfrag(base[1][a], v1, 0),
             qfrag(base[0][a], v0, 1), qfrag(base[1][a], v1, 1), qv.x, qv.y);
    v0 = (G == 0) ? base[2][a] : win[2][wi];
    v1 = (G == 0) ? base[3][a] : win[3][wi];
    mma16816(res[1][0], qfrag(base[2][a], v0, 0), qfrag(base[3][a], v1, 0),
             qfrag(base[2][a], v0, 1), qfrag(base[3][a], v1, 1), qv.x, qv.y);
}

template <int T0>
__device__ __forceinline__ void qtf4(const uint32_t (&base)[4][4],
                                     const uint32_t (&win)[4][4],
                                     float (&res)[2][2][4], const uint2* BT2) {
    qtf<T0>(base, win, res, BT2);
    qtf<T0 + 1>(base, win, res, BT2);
    qtf<T0 + 2>(base, win, res, BT2);
    qtf<T0 + 3>(base, win, res, BT2);
}

// ---- runtime W for B-table init (identical to R11/R13/R16; dups get 0) ----
__device__ float wsym(const float* __restrict__ W, int i, int m, int n) {
    if (i == m) return __ldg(&W[(33 + i * 32 + i) * 32 + n]);
    return __ldg(&W[(33 + i * 32 + m) * 32 + n]) + __ldg(&W[(33 + m * 32 + i) * 32 + n]);
}

__device__ float wcell(const float* __restrict__ W, int S, int c, int j, int n) {
    if (S >= 77) return 0.0f;
    if (S == 76) return (j == 0 && c == 0) ? __ldg(&W[n]) : 0.0f;
    if (S >= 72) {
        const int pv = ((S - 72) + 4 * c) & 15;
        return __ldg(&W[(1 + 2 * pv + j) * 32 + n]);
    }
    const int d = S >> 3, a = (S >> 1) & 3, h = S & 1;
    const int A = (a + 4 * c) & 15;
    if (d == 0) {
        if (h == 1 && j == 0) return 0.0f;           // dup {2A+1, 2A}
        return wsym(W, 2 * A + h, 2 * A + j, n);
    }
    if (d == 8 && A >= 8) return 0.0f;               // reversed copy of {A-8, A}
    const int B = (A + d) & 15;
    return wsym(W, 2 * A + h, 2 * B + j, n);
}

} // namespace

// B-fragment tables: [0, NKT*32) = Lo (n 0..15), [NKT*32, 2*NKT*32) = Hi.
__device__ uint4 g_Bf[2 * NKT * 32];

__global__ void bf_init_kernel(const float* __restrict__ W) {
    const int idx = blockIdx.x * blockDim.x + threadIdx.x;
    if (idx >= 2 * NKT * 32) return;
    const int t   = idx / (NKT * 32);
    const int rem = idx - t * (NKT * 32);
    const int kt  = rem >> 5;
    const int l   = rem & 31;
    const int c   = l & 3;
    const int n0  = (l >> 2) + t * 16;
    uint4 q;
    q.x = pack2(wcell(W, 2 * kt,     c, 0, n0),     wcell(W, 2 * kt,     c, 1, n0));
    q.y = pack2(wcell(W, 2 * kt + 1, c, 0, n0),     wcell(W, 2 * kt + 1, c, 1, n0));
    q.z = pack2(wcell(W, 2 * kt,     c, 0, n0 + 8), wcell(W, 2 * kt,     c, 1, n0 + 8));
    q.w = pack2(wcell(W, 2 * kt + 1, c, 0, n0 + 8), wcell(W, 2 * kt + 1, c, 1, n0 + 8));
    g_Bf[idx] = q;
}

__global__ void __launch_bounds__(256, 3)
tmpnn_kernel(const float* __restrict__ X, float* __restrict__ out)
{
    extern __shared__ char smem[];
    uint32_t* xsb = reinterpret_cast<uint32_t*>(smem);   // 2 buffers [128][20]

    const int tid  = threadIdx.x;
    const int lane = tid & 31;
    const int w    = tid >> 5;
    const int wp   = w & 1;                  // 0: n 0..15 (BfL), 1: n 16..31 (BfH)
    const int pair = w >> 1;                 // 4 pairs, 32 rows each
    const int c    = lane & 3;               // fragment column group / rotation
    const int r0   = pair * 32 + (lane >> 2);// rows r0, +8, +16, +24
    const int cb   = c * 2;

    // ---- stage bf16x2 X into buffer 0; init this warp's fp32 state in res ----
    const float* Xb = X + (size_t)blockIdx.x * (ROWS * 32);
    for (int i = tid; i < ROWS * 16; i += 256) {
        const int rr = i >> 4, j = i & 15;
        const float2 v = __ldg(reinterpret_cast<const float2*>(Xb + rr * 32 + 2 * j));
        xsb[rr * XBSTR + j] = pack2(v.x, v.y);
    }
    float res[2][2][4];
    #pragma unroll
    for (int g = 0; g < 2; ++g)
        #pragma unroll
        for (int nt = 0; nt < 2; ++nt) {
            const int cc = wp * 16 + nt * 8 + cb;
            const int rg = r0 + 16 * g;
            const float2 v0 = __ldg(reinterpret_cast<const float2*>(Xb + rg * 32 + cc));
            const float2 v1 = __ldg(reinterpret_cast<const float2*>(Xb + (rg + 8) * 32 + cc));
            res[g][nt][0] = v0.x; res[g][nt][1] = v0.y;
            res[g][nt][2] = v1.x; res[g][nt][3] = v1.y;
        }
    __syncthreads();   // buffer 0 visible (only CTA-wide barrier)

    const uint4* BT = g_Bf + (wp ? NKT * 32 : 0) + lane;

    for (int step = 0; step < 6; ++step) {
        const uint32_t* xb  = xsb + (step & 1) * XB_BUF;        // read buffer
        uint32_t*       xbn = xsb + ((step + 1) & 1) * XB_BUF;  // write buffer

        // base = y[0..3] for the 4 row slices (uint4, 16B-aligned: XBSTR=20)
        uint32_t base[4][4];
        #pragma unroll
        for (int s = 0; s < 4; ++s) {
            const uint4 t4 = *reinterpret_cast<const uint4*>(
                &xb[(r0 + 8 * s) * XBSTR + 4 * c]);
            base[s][0] = t4.x; base[s][1] = t4.y;
            base[s][2] = t4.z; base[s][3] = t4.w;
        }

        run_pass(BT, base, res, xb, r0, c);   // res += poly @ W (this n-half)

        // epilogue: pack updated state into the NEXT buffer (own cols only)
        #pragma unroll
        for (int g = 0; g < 2; ++g)
            #pragma unroll
            for (int nt = 0; nt < 2; ++nt) {
                const int pc = wp * 8 + nt * 4 + c;
                const int rg = r0 + 16 * g;
                xbn[rg * XBSTR + pc]       = pack2(res[g][nt][0], res[g][nt][1]);
                xbn[(rg + 8) * XBSTR + pc] = pack2(res[g][nt][2], res[g][nt][3]);
            }
        asm volatile("bar.sync %0, 64;" :: "r"(1 + pair) : "memory");
    }

    // ---- final step (step 6, reads buffer 0): even warps only, nt0 only ----
    if (wp == 0) {
        const uint32_t* xb = xsb + 0 * XB_BUF;
        uint32_t base[4][4];
        #pragma unroll
        for (int s = 0; s < 4; ++s) {
            const uint4 t4 = *reinterpret_cast<const uint4*>(
                &xb[(r0 + 8 * s) * XBSTR + 4 * c]);
            base[s][0] = t4.x; base[s][1] = t4.y;
            base[s][2] = t4.z; base[s][3] = t4.w;
        }
        const uint2* BT2 = reinterpret_cast<const uint2*>(g_Bf) + lane * 2;
        uint32_t win[4][4];
        #pragma unroll
        for (int s = 0; s < 4; ++s) {
            win[s][0] = base[s][0]; win[s][1] = base[s][1];
            win[s][2] = base[s][2]; win[s][3] = base[s][3];
        }
        qtf4<0>(base, win, res, BT2);   wload<1>(win, xb, r0, c);
        qtf4<4>(base, win, res, BT2);   wload<2>(win, xb, r0, c);
        qtf4<8>(base, win, res, BT2);   wload<3>(win, xb, r0, c);
        qtf4<12>(base, win, res, BT2);  wload<4>(win, xb, r0, c);
        qtf4<16>(base, win, res, BT2);  wload<5>(win, xb, r0, c);
        qtf4<20>(base, win, res, BT2);  wload<6>(win, xb, r0, c);
        qtf4<24>(base, win, res, BT2);  wload<7>(win, xb, r0, c);
        qtf4<28>(base, win, res, BT2);  wload<8>(win, xb, r0, c);
        qtf4<32>(base, win, res, BT2);
        {   // linear tiles 36, 37 + bias 38 (nt0 only)
            const uint2 q36 = __ldg(BT2 + 36 * 64);
            mma16816(res[0][0], base[0][0], base[1][0], base[0][1], base[1][1], q36.x, q36.y);
            mma16816(res[1][0], base[2][0], base[3][0], base[2][1], base[3][1], q36.x, q36.y);
            const uint2 q37 = __ldg(BT2 + 37 * 64);
            mma16816(res[0][0], base[0][2], base[1][2], base[0][3], base[1][3], q37.x, q37.y);
            mma16816(res[1][0], base[2][2], base[3][2], base[2][3], base[3][3], q37.x, q37.y);
            const uint2 q38 = __ldg(BT2 + 38 * 64);
            const uint32_t ab = 0x00003F80u, az = 0u;
            mma16816(res[0][0], ab, ab, az, az, q38.x, q38.y);
            mma16816(res[1][0], ab, ab, az, az, q38.x, q38.y);
        }
        if (c == 0) {
            const size_t ob = (size_t)blockIdx.x * ROWS;
            out[ob + r0]      = res[0][0][0];
            out[ob + r0 + 8]  = res[0][0][2];
            out[ob + r0 + 16] = res[1][0][0];
            out[ob + r0 + 24] = res[1][0][2];
        }
    }
}

extern "C" void kernel_launch(void* const* d_in, const int* in_sizes, int n_in,
                              void* d_out, int out_size) {
    const float* X = (const float*)d_in[0];
    const float* W = (const float*)d_in[1];
    float* out = (float*)d_out;
    const int rows = in_sizes[0] / 32;
    const int blocks = rows / ROWS;
    bf_init_kernel<<<(2 * NKT * 32 + 255) / 256, 256>>>(W);
    cudaFuncSetAttribute(tmpnn_kernel, cudaFuncAttributeMaxDynamicSharedMemorySize,
                         SMEM_BYTES);
    tmpnn_kernel<<<blocks, 256, SMEM_BYTES>>>(X, out);
}